// round 10
// baseline (speedup 1.0000x reference)
#include <cuda_runtime.h>
#include <cstdint>

// TransD forward, simplified (eye is identity, RD==ED):
//   h_out = renorm(rp) * <renorm(hp), renorm(hv)> + renorm(hv)
//   rv_out = renorm(rv)
//   t_out = renorm(rp) * <renorm(tp), renorm(tv)> + renorm(tv)
//
// One warp per sample. Gathers go through cp.async.bulk (TMA bulk engine,
// deep outstanding-request queue) into SMEM instead of LDG (LSU queue-bound).
// mbarrier completion per warp, then 9-SHFL packed reduction.

#define NB 8192
#define DV 32u          // float4s per 128-float row
#define ROW_BYTES 512u  // 128 floats
#define FULL 0xffffffffu
#define WPB 4           // warps per block (128 threads)

__device__ __forceinline__ float dot4(float4 a, float4 b) {
    return a.x * b.x + a.y * b.y + a.z * b.z + a.w * b.w;
}

__device__ __forceinline__ float rscale(float sumsq) {
    float n = sqrtf(sumsq);
    return (n > 1.0f) ? (1.0f / (n + 1e-7f)) : 1.0f;
}

__device__ __forceinline__ void st_cs(float4* p, float4 v) {
    asm volatile("st.global.cs.v4.f32 [%0], {%1,%2,%3,%4};"
                 :: "l"(p), "f"(v.x), "f"(v.y), "f"(v.z), "f"(v.w) : "memory");
}

__device__ __forceinline__ uint32_t smem_u32(const void* p) {
    uint32_t a;
    asm("{ .reg .u64 tmp; cvta.to.shared.u64 tmp, %1; cvt.u32.u64 %0, tmp; }"
        : "=r"(a) : "l"(p));
    return a;
}

__device__ __forceinline__ void bulk_cp(uint32_t dst_smem, const void* src,
                                        uint32_t bytes, uint32_t mbar) {
    asm volatile(
        "cp.async.bulk.shared::cluster.global.mbarrier::complete_tx::bytes "
        "[%0], [%1], %2, [%3];"
        :: "r"(dst_smem), "l"(src), "r"(bytes), "r"(mbar) : "memory");
}

__global__ __launch_bounds__(WPB * 32) void transd_kernel(
    const char* __restrict__ ee,    // entity_emb      (row = 512B)
    const char* __restrict__ eep,   // entity_emb_p
    const char* __restrict__ re,    // relation_emb
    const char* __restrict__ rep,   // relation_emb_p
    const int* __restrict__ h,
    const int* __restrict__ r,
    const int* __restrict__ t,
    float4* __restrict__ out)       // [3 * NB * 32]
{
    // per-warp staging: 6 rows x 512B
    __shared__ __align__(16) float4 buf[WPB][6 * 32];
    __shared__ __align__(8) unsigned long long mbar[WPB];

    int wid  = threadIdx.x >> 5;
    unsigned lane = threadIdx.x & 31u;
    int gwarp = blockIdx.x * WPB + wid;
    if (gwarp >= NB) return;

    uint32_t mb = smem_u32(&mbar[wid]);

    if (lane == 0) {
        asm volatile("mbarrier.init.shared.b64 [%0], 1;" :: "r"(mb) : "memory");
        asm volatile("fence.proxy.async.shared::cta;" ::: "memory");
    }
    __syncwarp();

    if (lane == 0) {
        int hi = __ldg(&h[gwarp]);
        int ri = __ldg(&r[gwarp]);
        int ti = __ldg(&t[gwarp]);

        asm volatile("mbarrier.arrive.expect_tx.shared.b64 _, [%0], %1;"
                     :: "r"(mb), "r"(6u * ROW_BYTES) : "memory");

        uint32_t d0 = smem_u32(&buf[wid][0]);
        bulk_cp(d0 + 0u * ROW_BYTES, ee  + (size_t)hi * ROW_BYTES, ROW_BYTES, mb);
        bulk_cp(d0 + 1u * ROW_BYTES, eep + (size_t)hi * ROW_BYTES, ROW_BYTES, mb);
        bulk_cp(d0 + 2u * ROW_BYTES, ee  + (size_t)ti * ROW_BYTES, ROW_BYTES, mb);
        bulk_cp(d0 + 3u * ROW_BYTES, eep + (size_t)ti * ROW_BYTES, ROW_BYTES, mb);
        bulk_cp(d0 + 4u * ROW_BYTES, re  + (size_t)ri * ROW_BYTES, ROW_BYTES, mb);
        bulk_cp(d0 + 5u * ROW_BYTES, rep + (size_t)ri * ROW_BYTES, ROW_BYTES, mb);
    }

    // all lanes wait for completion (phase 0, single-shot)
    {
        uint32_t done;
        asm volatile(
            "{\n\t.reg .pred p;\n\t"
            "mbarrier.try_wait.parity.acquire.cta.shared::cta.b64 p, [%1], 0;\n\t"
            "selp.b32 %0, 1, 0, p;\n\t}"
            : "=r"(done) : "r"(mb) : "memory");
        if (!done) {
            asm volatile(
                "{\n\t.reg .pred P1;\n\t"
                "WL_%=:\n\t"
                "mbarrier.try_wait.parity.acquire.cta.shared::cta.b64 P1, [%0], 0, 0x989680;\n\t"
                "@P1 bra.uni WD_%=;\n\t"
                "bra.uni WL_%=;\n\t"
                "WD_%=:\n\t}"
                :: "r"(mb) : "memory");
        }
    }

    float4 hv = buf[wid][0 * 32 + lane];
    float4 hp = buf[wid][1 * 32 + lane];
    float4 tv = buf[wid][2 * 32 + lane];
    float4 tp = buf[wid][3 * 32 + lane];
    float4 rv = buf[wid][4 * 32 + lane];
    float4 rp = buf[wid][5 * 32 + lane];

    // 8 per-lane partials:
    // 0:|hv|^2 1:|hp|^2 2:|tv|^2 3:|tp|^2 4:|rv|^2 5:|rp|^2 6:<hp,hv> 7:<tp,tv>
    float p0 = dot4(hv, hv);
    float p1 = dot4(hp, hp);
    float p2 = dot4(tv, tv);
    float p3 = dot4(tp, tp);
    float p4 = dot4(rv, rv);
    float p5 = dot4(rp, rp);
    float p6 = dot4(hp, hv);
    float p7 = dot4(tp, tv);

    bool b0 = lane & 1u;
    bool b1 = lane & 2u;
    bool b2 = lane & 4u;

    // value-packing butterfly: 8 sums in 9 SHFLs
    float q0 = (b0 ? p1 : p0) + __shfl_xor_sync(FULL, b0 ? p0 : p1, 1);
    float q1 = (b0 ? p3 : p2) + __shfl_xor_sync(FULL, b0 ? p2 : p3, 1);
    float q2 = (b0 ? p5 : p4) + __shfl_xor_sync(FULL, b0 ? p4 : p5, 1);
    float q3 = (b0 ? p7 : p6) + __shfl_xor_sync(FULL, b0 ? p6 : p7, 1);

    float u0 = (b1 ? q1 : q0) + __shfl_xor_sync(FULL, b1 ? q0 : q1, 2);
    float u1 = (b1 ? q3 : q2) + __shfl_xor_sync(FULL, b1 ? q2 : q3, 2);

    float w = (b2 ? u1 : u0) + __shfl_xor_sync(FULL, b2 ? u0 : u1, 4);
    w += __shfl_xor_sync(FULL, w, 8);
    w += __shfl_xor_sync(FULL, w, 16);
    // every lane holds total_{lane&7}

    float rs = rscale(w);

    float c_hv = __shfl_sync(FULL, rs, 0);
    float c_hp = __shfl_sync(FULL, rs, 1);
    float c_tv = __shfl_sync(FULL, rs, 2);
    float c_tp = __shfl_sync(FULL, rs, 3);
    float c_rv = __shfl_sync(FULL, rs, 4);
    float c_rp = __shfl_sync(FULL, rs, 5);
    float d_h  = __shfl_sync(FULL, w, 6);
    float d_t  = __shfl_sync(FULL, w, 7);

    float a_h = c_rp * (d_h * c_hp * c_hv);
    float a_t = c_rp * (d_t * c_tp * c_tv);

    unsigned base = (unsigned)gwarp * DV + lane;

    float4 o;
    o.x = rp.x * a_h + hv.x * c_hv;
    o.y = rp.y * a_h + hv.y * c_hv;
    o.z = rp.z * a_h + hv.z * c_hv;
    o.w = rp.w * a_h + hv.w * c_hv;
    st_cs(&out[base], o);

    o.x = rv.x * c_rv; o.y = rv.y * c_rv; o.z = rv.z * c_rv; o.w = rv.w * c_rv;
    st_cs(&out[NB * DV + base], o);

    o.x = rp.x * a_t + tv.x * c_tv;
    o.y = rp.y * a_t + tv.y * c_tv;
    o.z = rp.z * a_t + tv.z * c_tv;
    o.w = rp.w * a_t + tv.w * c_tv;
    st_cs(&out[2u * NB * DV + base], o);
}

extern "C" void kernel_launch(void* const* d_in, const int* in_sizes, int n_in,
                              void* d_out, int out_size) {
    const char* ee  = (const char*)d_in[0];
    const char* eep = (const char*)d_in[1];
    const char* re  = (const char*)d_in[2];
    const char* rep = (const char*)d_in[3];
    const int* h = (const int*)d_in[4];
    const int* r = (const int*)d_in[5];
    const int* t = (const int*)d_in[6];

    int blocks = (NB + WPB - 1) / WPB;  // 2048 blocks of 128 threads
    transd_kernel<<<blocks, WPB * 32>>>(ee, eep, re, rep, h, r, t, (float4*)d_out);
}

// round 11
// speedup vs baseline: 1.1985x; 1.1985x over previous
#include <cuda_runtime.h>

// TransD forward, simplified (eye is identity, RD==ED):
//   h_out = renorm(rp) * <renorm(hp), renorm(hv)> + renorm(hv)
//   rv_out = renorm(rv)
//   t_out = renorm(rp) * <renorm(tp), renorm(tv)> + renorm(tv)
//
// ILP=2 single-wave: one warp handles 2 samples, 12 gathers issued up front,
// two 9-SHFL packed reduction trees. 128-thread blocks + launch_bounds(128,8)
// force <=64 regs so 32 warps/SM resident -> grid (4096 warps) fits one wave.

#define NB 8192
#define DV 32u  // float4s per 128-float row
#define FULL 0xffffffffu

__device__ __forceinline__ float dot4(float4 a, float4 b) {
    return a.x * b.x + a.y * b.y + a.z * b.z + a.w * b.w;
}

__device__ __forceinline__ float rscale(float sumsq) {
    float n = sqrtf(sumsq);
    return (n > 1.0f) ? (1.0f / (n + 1e-7f)) : 1.0f;
}

__device__ __forceinline__ void st_cs(float4* p, float4 v) {
    asm volatile("st.global.cs.v4.f32 [%0], {%1,%2,%3,%4};"
                 :: "l"(p), "f"(v.x), "f"(v.y), "f"(v.z), "f"(v.w) : "memory");
}

// 8 simultaneous warp sums in 9 SHFLs; returns total_{lane&7} per lane.
__device__ __forceinline__ float packed_reduce8(
    float p0, float p1, float p2, float p3,
    float p4, float p5, float p6, float p7, unsigned lane)
{
    bool b0 = lane & 1u;
    bool b1 = lane & 2u;
    bool b2 = lane & 4u;
    float q0 = (b0 ? p1 : p0) + __shfl_xor_sync(FULL, b0 ? p0 : p1, 1);
    float q1 = (b0 ? p3 : p2) + __shfl_xor_sync(FULL, b0 ? p2 : p3, 1);
    float q2 = (b0 ? p5 : p4) + __shfl_xor_sync(FULL, b0 ? p4 : p5, 1);
    float q3 = (b0 ? p7 : p6) + __shfl_xor_sync(FULL, b0 ? p6 : p7, 1);
    float u0 = (b1 ? q1 : q0) + __shfl_xor_sync(FULL, b1 ? q0 : q1, 2);
    float u1 = (b1 ? q3 : q2) + __shfl_xor_sync(FULL, b1 ? q2 : q3, 2);
    float w  = (b2 ? u1 : u0) + __shfl_xor_sync(FULL, b2 ? u0 : u1, 4);
    w += __shfl_xor_sync(FULL, w, 8);
    w += __shfl_xor_sync(FULL, w, 16);
    return w;
}

__global__ __launch_bounds__(128, 8) void transd_kernel(
    const float4* __restrict__ ee,   // entity_emb      [ENT*32]
    const float4* __restrict__ eep,  // entity_emb_p    [ENT*32]
    const float4* __restrict__ re,   // relation_emb    [REL*32]
    const float4* __restrict__ rep,  // relation_emb_p  [REL*32]
    const int* __restrict__ h,
    const int* __restrict__ r,
    const int* __restrict__ t,
    float4* __restrict__ out)        // [3 * NB * 32]
{
    int gwarp = (blockIdx.x * blockDim.x + threadIdx.x) >> 5;
    unsigned lane = threadIdx.x & 31u;
    int s0 = gwarp * 2;
    int s1 = s0 + 1;
    if (s0 >= NB) return;

    int hi0 = __ldg(&h[s0]), hi1 = __ldg(&h[s1]);
    int ri0 = __ldg(&r[s0]), ri1 = __ldg(&r[s1]);
    int ti0 = __ldg(&t[s0]), ti1 = __ldg(&t[s1]);

    unsigned oh0 = (unsigned)hi0 * DV + lane;
    unsigned ot0 = (unsigned)ti0 * DV + lane;
    unsigned or0 = (unsigned)ri0 * DV + lane;
    unsigned oh1 = (unsigned)hi1 * DV + lane;
    unsigned ot1 = (unsigned)ti1 * DV + lane;
    unsigned or1 = (unsigned)ri1 * DV + lane;

    // all 12 gathers issued before any dependent use
    float4 hv0 = __ldg(ee  + oh0);
    float4 hp0 = __ldg(eep + oh0);
    float4 tv0 = __ldg(ee  + ot0);
    float4 tp0 = __ldg(eep + ot0);
    float4 rv0 = __ldg(re  + or0);
    float4 rp0 = __ldg(rep + or0);
    float4 hv1 = __ldg(ee  + oh1);
    float4 hp1 = __ldg(eep + oh1);
    float4 tv1 = __ldg(ee  + ot1);
    float4 tp1 = __ldg(eep + ot1);
    float4 rv1 = __ldg(re  + or1);
    float4 rp1 = __ldg(rep + or1);

    // ---- sample 0 reduction ----
    float w0 = packed_reduce8(
        dot4(hv0, hv0), dot4(hp0, hp0), dot4(tv0, tv0), dot4(tp0, tp0),
        dot4(rv0, rv0), dot4(rp0, rp0), dot4(hp0, hv0), dot4(tp0, tv0), lane);
    // ---- sample 1 reduction ----
    float w1 = packed_reduce8(
        dot4(hv1, hv1), dot4(hp1, hp1), dot4(tv1, tv1), dot4(tp1, tp1),
        dot4(rv1, rv1), dot4(rp1, rp1), dot4(hp1, hv1), dot4(tp1, tv1), lane);

    float rs0 = rscale(w0);
    float rs1 = rscale(w1);

    // sample 0 coefficients
    float c_hv0 = __shfl_sync(FULL, rs0, 0);
    float c_hp0 = __shfl_sync(FULL, rs0, 1);
    float c_tv0 = __shfl_sync(FULL, rs0, 2);
    float c_tp0 = __shfl_sync(FULL, rs0, 3);
    float c_rv0 = __shfl_sync(FULL, rs0, 4);
    float c_rp0 = __shfl_sync(FULL, rs0, 5);
    float d_h0  = __shfl_sync(FULL, w0, 6);
    float d_t0  = __shfl_sync(FULL, w0, 7);
    // sample 1 coefficients
    float c_hv1 = __shfl_sync(FULL, rs1, 0);
    float c_hp1 = __shfl_sync(FULL, rs1, 1);
    float c_tv1 = __shfl_sync(FULL, rs1, 2);
    float c_tp1 = __shfl_sync(FULL, rs1, 3);
    float c_rv1 = __shfl_sync(FULL, rs1, 4);
    float c_rp1 = __shfl_sync(FULL, rs1, 5);
    float d_h1  = __shfl_sync(FULL, w1, 6);
    float d_t1  = __shfl_sync(FULL, w1, 7);

    float a_h0 = c_rp0 * (d_h0 * c_hp0 * c_hv0);
    float a_t0 = c_rp0 * (d_t0 * c_tp0 * c_tv0);
    float a_h1 = c_rp1 * (d_h1 * c_hp1 * c_hv1);
    float a_t1 = c_rp1 * (d_t1 * c_tp1 * c_tv1);

    unsigned b0 = (unsigned)s0 * DV + lane;
    unsigned b1 = (unsigned)s1 * DV + lane;

    float4 o;
    o.x = rp0.x * a_h0 + hv0.x * c_hv0;
    o.y = rp0.y * a_h0 + hv0.y * c_hv0;
    o.z = rp0.z * a_h0 + hv0.z * c_hv0;
    o.w = rp0.w * a_h0 + hv0.w * c_hv0;
    st_cs(&out[b0], o);
    o.x = rp1.x * a_h1 + hv1.x * c_hv1;
    o.y = rp1.y * a_h1 + hv1.y * c_hv1;
    o.z = rp1.z * a_h1 + hv1.z * c_hv1;
    o.w = rp1.w * a_h1 + hv1.w * c_hv1;
    st_cs(&out[b1], o);

    o.x = rv0.x * c_rv0; o.y = rv0.y * c_rv0; o.z = rv0.z * c_rv0; o.w = rv0.w * c_rv0;
    st_cs(&out[NB * DV + b0], o);
    o.x = rv1.x * c_rv1; o.y = rv1.y * c_rv1; o.z = rv1.z * c_rv1; o.w = rv1.w * c_rv1;
    st_cs(&out[NB * DV + b1], o);

    o.x = rp0.x * a_t0 + tv0.x * c_tv0;
    o.y = rp0.y * a_t0 + tv0.y * c_tv0;
    o.z = rp0.z * a_t0 + tv0.z * c_tv0;
    o.w = rp0.w * a_t0 + tv0.w * c_tv0;
    st_cs(&out[2u * NB * DV + b0], o);
    o.x = rp1.x * a_t1 + tv1.x * c_tv1;
    o.y = rp1.y * a_t1 + tv1.y * c_tv1;
    o.z = rp1.z * a_t1 + tv1.z * c_tv1;
    o.w = rp1.w * a_t1 + tv1.w * c_tv1;
    st_cs(&out[2u * NB * DV + b1], o);
}

extern "C" void kernel_launch(void* const* d_in, const int* in_sizes, int n_in,
                              void* d_out, int out_size) {
    const float4* ee  = (const float4*)d_in[0];
    const float4* eep = (const float4*)d_in[1];
    const float4* re  = (const float4*)d_in[2];
    const float4* rep = (const float4*)d_in[3];
    const int* h = (const int*)d_in[4];
    const int* r = (const int*)d_in[5];
    const int* t = (const int*)d_in[6];

    // 2 samples/warp -> 4096 warps -> 1024 blocks of 128 threads
    int blocks = (NB / 2 * 32 + 127) / 128;
    transd_kernel<<<blocks, 128>>>(ee, eep, re, rep, h, r, t, (float4*)d_out);
}